// round 1
// baseline (speedup 1.0000x reference)
#include <cuda_runtime.h>
#include <cstdint>

// RNNModel: g = [E|R]@[We|Wr]^T + (be+br+bh)  (proj, relu on t==0 rows)
//           h_t = relu(g_t + h_{t-1}@Wh^T)    (7 in-place GEMM launches)
//           need = h_7^T                       (tiled transpose)
// TF32 mma.sync.m16n8k8, 128x128x32 CTA tiles, 8 warps, SKEW=36 smem.

#define SKEW 36

__device__ __forceinline__ unsigned f2tf(float x) {
    unsigned u;
    asm("cvt.rna.tf32.f32 %0, %1;" : "=r"(u) : "f"(x));
    return u;
}

__device__ __forceinline__ void mma_tf32(float c[4], const unsigned a[4], const unsigned b[2]) {
    asm volatile(
        "mma.sync.aligned.m16n8k8.row.col.f32.tf32.tf32.f32 "
        "{%0,%1,%2,%3}, {%4,%5,%6,%7}, {%8,%9}, {%0,%1,%2,%3};\n"
        : "+f"(c[0]), "+f"(c[1]), "+f"(c[2]), "+f"(c[3])
        : "r"(a[0]), "r"(a[1]), "r"(a[2]), "r"(a[3]),
          "r"(b[0]), "r"(b[1]));
}

// MODE 0: projection  C[65536,1024] = [E|R] @ [We|Wr]^T + (be+br+bh); relu on rows with row%8==0
// MODE 1: recurrence  C rows (stride 8192) = relu(C + A @ Wh^T), A stride 8192
template<int MODE>
__global__ __launch_bounds__(256, 1)
void gemm_k(const float* A0, const float* A1,
            const float* __restrict__ B0, const float* __restrict__ B1,
            const float* __restrict__ be, const float* __restrict__ br,
            const float* __restrict__ bhp,
            float* C)
{
    constexpr int KTOT = (MODE == 0) ? 1536 : 1024;
    constexpr int LDC  = (MODE == 0) ? 1024 : 8192;

    __shared__ unsigned sA[128 * SKEW];
    __shared__ unsigned sB[128 * SKEW];
    __shared__ float sBias[128];

    const int tid = threadIdx.x;
    const int bN  = blockIdx.x;   // N tile (0..7)
    const int bM  = blockIdx.y;   // M tile

    if (MODE == 0) {
        if (tid < 128) {
            int c = bN * 128 + tid;
            sBias[tid] = be[c] + br[c] + bhp[c];
        }
    }

    const int lane = tid & 31;
    const int warp = tid >> 5;
    const int wm = warp & 3;      // 4 M-warps of 32 rows
    const int wn = warp >> 2;     // 2 N-warps of 64 cols
    const int grp = lane >> 2;    // 0..7
    const int qid = lane & 3;     // 0..3

    int lrow[4], lc4[4];
    #pragma unroll
    for (int i = 0; i < 4; ++i) {
        int f = tid + i * 256;
        lrow[i] = f >> 3;
        lc4[i]  = (f & 7) * 4;
    }

    float4 ra[4], rb[4];

    auto loadA = [&](int kt) {
        #pragma unroll
        for (int i = 0; i < 4; ++i) {
            int gr = bM * 128 + lrow[i];
            int gk = kt * 32 + lc4[i];
            const float* p;
            if (MODE == 0) {
                p = (gk < 512) ? (A0 + (size_t)gr * 512 + gk)
                               : (A1 + (size_t)gr * 1024 + (gk - 512));
            } else {
                p = A0 + (size_t)gr * 8192 + gk;
            }
            ra[i] = *(const float4*)p;
        }
    };
    auto loadB = [&](int kt) {
        #pragma unroll
        for (int i = 0; i < 4; ++i) {
            int gn = bN * 128 + lrow[i];
            int gk = kt * 32 + lc4[i];
            const float* p;
            if (MODE == 0) {
                p = (gk < 512) ? (B0 + (size_t)gn * 512 + gk)
                               : (B1 + (size_t)gn * 1024 + (gk - 512));
            } else {
                p = B0 + (size_t)gn * 1024 + gk;
            }
            rb[i] = *(const float4*)p;
        }
    };

    float acc[2][8][4];
    #pragma unroll
    for (int mt = 0; mt < 2; ++mt)
        #pragma unroll
        for (int nt = 0; nt < 8; ++nt)
            #pragma unroll
            for (int j = 0; j < 4; ++j) acc[mt][nt][j] = 0.f;

    loadA(0); loadB(0);

    constexpr int NKT = KTOT / 32;
    for (int kt = 0; kt < NKT; ++kt) {
        #pragma unroll
        for (int i = 0; i < 4; ++i) {
            unsigned* pa = &sA[lrow[i] * SKEW + lc4[i]];
            pa[0] = f2tf(ra[i].x); pa[1] = f2tf(ra[i].y);
            pa[2] = f2tf(ra[i].z); pa[3] = f2tf(ra[i].w);
            unsigned* pb = &sB[lrow[i] * SKEW + lc4[i]];
            pb[0] = f2tf(rb[i].x); pb[1] = f2tf(rb[i].y);
            pb[2] = f2tf(rb[i].z); pb[3] = f2tf(rb[i].w);
        }
        __syncthreads();
        if (kt + 1 < NKT) { loadA(kt + 1); loadB(kt + 1); }

        #pragma unroll
        for (int ks = 0; ks < 4; ++ks) {
            int k0 = ks * 8 + qid;
            unsigned afr[2][4];
            #pragma unroll
            for (int mt = 0; mt < 2; ++mt) {
                int r = wm * 32 + mt * 16 + grp;
                afr[mt][0] = sA[r * SKEW + k0];
                afr[mt][1] = sA[(r + 8) * SKEW + k0];
                afr[mt][2] = sA[r * SKEW + k0 + 4];
                afr[mt][3] = sA[(r + 8) * SKEW + k0 + 4];
            }
            unsigned bfr[8][2];
            #pragma unroll
            for (int nt = 0; nt < 8; ++nt) {
                int n = wn * 64 + nt * 8 + grp;
                bfr[nt][0] = sB[n * SKEW + k0];
                bfr[nt][1] = sB[n * SKEW + k0 + 4];
            }
            #pragma unroll
            for (int mt = 0; mt < 2; ++mt)
                #pragma unroll
                for (int nt = 0; nt < 8; ++nt)
                    mma_tf32(acc[mt][nt], afr[mt], bfr[nt]);
        }
        __syncthreads();
    }

    // epilogue
    #pragma unroll
    for (int mt = 0; mt < 2; ++mt) {
        int r0 = bM * 128 + wm * 32 + mt * 16 + grp;
        #pragma unroll
        for (int nt = 0; nt < 8; ++nt) {
            int col  = bN * 128 + wn * 64 + nt * 8 + qid * 2;
            int colL = wn * 64 + nt * 8 + qid * 2;
            if (MODE == 0) {
                float b0 = sBias[colL];
                float b1 = sBias[colL + 1];
                float x0 = acc[mt][nt][0] + b0;
                float x1 = acc[mt][nt][1] + b1;
                float x2 = acc[mt][nt][2] + b0;
                float x3 = acc[mt][nt][3] + b1;
                if (grp == 0) {   // r0 % 8 == 0  ->  t == 0 rows: apply relu (step 0 folded)
                    x0 = fmaxf(x0, 0.f); x1 = fmaxf(x1, 0.f);
                    x2 = fmaxf(x2, 0.f); x3 = fmaxf(x3, 0.f);
                }
                *(float2*)(C + (size_t)r0 * LDC + col)       = make_float2(x0, x1);
                *(float2*)(C + (size_t)(r0 + 8) * LDC + col) = make_float2(x2, x3);
            } else {
                float* p0 = C + (size_t)r0 * LDC + col;
                float* p1 = C + (size_t)(r0 + 8) * LDC + col;
                float2 g0 = *(float2*)p0;
                float2 g1 = *(float2*)p1;
                *(float2*)p0 = make_float2(fmaxf(acc[mt][nt][0] + g0.x, 0.f),
                                           fmaxf(acc[mt][nt][1] + g0.y, 0.f));
                *(float2*)p1 = make_float2(fmaxf(acc[mt][nt][2] + g1.x, 0.f),
                                           fmaxf(acc[mt][nt][3] + g1.y, 0.f));
            }
        }
    }
}

// need[h, b] = out[b, 7, h]   (out row stride 8192, t=7 offset 7168)
__global__ void transpose_k(const float* __restrict__ out, float* __restrict__ need)
{
    __shared__ float tile[32][33];
    int h0 = blockIdx.x * 32;
    int b0 = blockIdx.y * 32;
    int x = threadIdx.x;
    int y = threadIdx.y;
    #pragma unroll
    for (int j = 0; j < 32; j += 8)
        tile[y + j][x] = out[(size_t)(b0 + y + j) * 8192 + 7168 + h0 + x];
    __syncthreads();
    #pragma unroll
    for (int j = 0; j < 32; j += 8)
        need[(size_t)(h0 + y + j) * 8192 + b0 + x] = tile[x][y + j];
}

extern "C" void kernel_launch(void* const* d_in, const int* in_sizes, int n_in,
                              void* d_out, int out_size)
{
    const float* entity   = (const float*)d_in[0];  // [8192, 8, 512]
    const float* relation = (const float*)d_in[1];  // [8192, 8, 1024]
    const float* We       = (const float*)d_in[2];  // [1024, 512]
    const float* be       = (const float*)d_in[3];  // [1024]
    const float* Wr       = (const float*)d_in[4];  // [1024, 1024]
    const float* br       = (const float*)d_in[5];  // [1024]
    const float* Wh       = (const float*)d_in[6];  // [1024, 1024]
    const float* bh       = (const float*)d_in[7];  // [1024]

    float* out  = (float*)d_out;              // [8192, 8, 1024] = [65536, 1024]
    float* need = out + (size_t)65536 * 1024;  // [1024, 8192]

    // Projection: g (with all biases folded, relu applied for t==0 rows)
    gemm_k<0><<<dim3(8, 512), 256>>>(entity, relation, We, Wr, be, br, bh, out);

    // Recurrence: t = 1..7, in place over the g slices
    for (int t = 1; t < 8; ++t) {
        const float* Aprev = out + (size_t)(t - 1) * 1024;
        float*       Ct    = out + (size_t)t * 1024;
        gemm_k<1><<<dim3(8, 64), 256>>>(Aprev, nullptr, Wh, nullptr,
                                        nullptr, nullptr, nullptr, Ct);
    }

    // need = h_7^T
    transpose_k<<<dim3(32, 256), dim3(32, 8)>>>(out, need);
}

// round 2
// speedup vs baseline: 1.1086x; 1.1086x over previous
#include <cuda_runtime.h>
#include <cstdint>

// RNNModel: g = [E|R]@[We|Wr]^T + (be+br+bh)  (proj, relu on t==0 rows)
//           h_t = relu(g_t + h_{t-1}@Wh^T)    (7 in-place GEMM launches)
//           need = h_7^T                       (tiled transpose)
// TF32 mma.sync.m16n8k8, 128x128x32 CTA tiles, 8 warps.
// R1: ldmatrix.x4.b16 fragment loads (tf32 quadrant trick) + double-buffered smem.

#define SKEW 36
#define BUFW (128 * SKEW)   // words per buffer per matrix

__device__ __forceinline__ unsigned f2tf(float x) {
    unsigned u;
    asm("cvt.rna.tf32.f32 %0, %1;" : "=r"(u) : "f"(x));
    return u;
}

__device__ __forceinline__ void mma_tf32(float c[4], const unsigned a[4], const unsigned b[2]) {
    asm volatile(
        "mma.sync.aligned.m16n8k8.row.col.f32.tf32.tf32.f32 "
        "{%0,%1,%2,%3}, {%4,%5,%6,%7}, {%8,%9}, {%0,%1,%2,%3};\n"
        : "+f"(c[0]), "+f"(c[1]), "+f"(c[2]), "+f"(c[3])
        : "r"(a[0]), "r"(a[1]), "r"(a[2]), "r"(a[3]),
          "r"(b[0]), "r"(b[1]));
}

__device__ __forceinline__ void ldsm_x4(unsigned& r0, unsigned& r1, unsigned& r2, unsigned& r3,
                                        unsigned addr) {
    asm volatile("ldmatrix.sync.aligned.m8n8.x4.shared.b16 {%0,%1,%2,%3}, [%4];\n"
                 : "=r"(r0), "=r"(r1), "=r"(r2), "=r"(r3)
                 : "r"(addr));
}

// MODE 0: projection  C[65536,1024] = [E|R] @ [We|Wr]^T + (be+br+bh); relu on rows with row%8==0
// MODE 1: recurrence  C rows (stride 8192) = relu(C + A @ Wh^T), A stride 8192
template<int MODE>
__global__ __launch_bounds__(256, 1)
void gemm_k(const float* A0, const float* A1,
            const float* __restrict__ B0, const float* __restrict__ B1,
            const float* __restrict__ be, const float* __restrict__ br,
            const float* __restrict__ bhp,
            float* C)
{
    constexpr int KTOT = (MODE == 0) ? 1536 : 1024;
    constexpr int LDC  = (MODE == 0) ? 1024 : 8192;

    extern __shared__ unsigned sh[];
    unsigned* sA = sh;               // [2][BUFW]
    unsigned* sB = sh + 2 * BUFW;    // [2][BUFW]
    float* sBias = (float*)(sh + 4 * BUFW);  // [128]

    const int tid = threadIdx.x;
    const int bN  = blockIdx.x;
    const int bM  = blockIdx.y;

    if (MODE == 0) {
        if (tid < 128) {
            int c = bN * 128 + tid;
            sBias[tid] = be[c] + br[c] + bhp[c];
        }
    }

    const int lane = tid & 31;
    const int warp = tid >> 5;
    const int wm = warp & 3;      // 4 M-warps of 32 rows
    const int wn = warp >> 2;     // 2 N-warps of 64 cols
    const int grp = lane >> 2;
    const int qid = lane & 3;

    int lrow[4], lc4[4], soff[4];
    #pragma unroll
    for (int i = 0; i < 4; ++i) {
        int f = tid + i * 256;
        lrow[i] = f >> 3;
        lc4[i]  = (f & 7) * 4;
        soff[i] = lrow[i] * SKEW + lc4[i];
    }

    // ldmatrix per-thread addresses (bytes, shared space), buffer 0.
    // A fragment {a0,a1,a2,a3}: quadrants (row+0,k0)(row+8,k0)(row+0,k4)(row+8,k4)
    //   -> thread group g=lane>>3 supplies row += (g&1)*8, koff = (g>>1)*4
    // B fragment pair {b0_e,b1_e,b0_o,b1_o}: (n+0,k0)(n+0,k4)(n+8,k0)(n+8,k4)
    //   -> row += (g>>1)*8, koff = (g&1)*4
    const unsigned aBase = (unsigned)__cvta_generic_to_shared(sA);
    const unsigned bBase = (unsigned)__cvta_generic_to_shared(sB);
    const int rA = wm * 32 + ((lane >> 3) & 1) * 8 + (lane & 7);
    const int kA = ((lane >> 4) & 1) * 4;
    unsigned aAddr[2];
    #pragma unroll
    for (int mt = 0; mt < 2; ++mt)
        aAddr[mt] = aBase + (unsigned)(((rA + mt * 16) * SKEW + kA) * 4);
    const int rB = wn * 64 + ((lane >> 4) & 1) * 8 + (lane & 7);
    const int kB = ((lane >> 3) & 1) * 4;
    unsigned bAddr[4];
    #pragma unroll
    for (int p = 0; p < 4; ++p)
        bAddr[p] = bBase + (unsigned)(((rB + p * 16) * SKEW + kB) * 4);

    float4 ra[4], rb[4];

    auto loadA = [&](int kt) {
        #pragma unroll
        for (int i = 0; i < 4; ++i) {
            int gr = bM * 128 + lrow[i];
            int gk = kt * 32 + lc4[i];
            const float* p;
            if (MODE == 0) {
                p = (gk < 512) ? (A0 + (size_t)gr * 512 + gk)
                               : (A1 + (size_t)gr * 1024 + (gk - 512));
            } else {
                p = A0 + (size_t)gr * 8192 + gk;
            }
            ra[i] = *(const float4*)p;
        }
    };
    auto loadB = [&](int kt) {
        #pragma unroll
        for (int i = 0; i < 4; ++i) {
            int gn = bN * 128 + lrow[i];
            int gk = kt * 32 + lc4[i];
            const float* p;
            if (MODE == 0) {
                p = (gk < 512) ? (B0 + (size_t)gn * 512 + gk)
                               : (B1 + (size_t)gn * 1024 + (gk - 512));
            } else {
                p = B0 + (size_t)gn * 1024 + gk;
            }
            rb[i] = *(const float4*)p;
        }
    };

    float acc[2][8][4];
    #pragma unroll
    for (int mt = 0; mt < 2; ++mt)
        #pragma unroll
        for (int nt = 0; nt < 8; ++nt)
            #pragma unroll
            for (int j = 0; j < 4; ++j) acc[mt][nt][j] = 0.f;

    loadA(0); loadB(0);

    constexpr int NKT = KTOT / 32;
    int buf = 0;
    for (int kt = 0; kt < NKT; ++kt) {
        const int bo = buf * BUFW;
        #pragma unroll
        for (int i = 0; i < 4; ++i) {
            uint4 va = make_uint4(f2tf(ra[i].x), f2tf(ra[i].y), f2tf(ra[i].z), f2tf(ra[i].w));
            uint4 vb = make_uint4(f2tf(rb[i].x), f2tf(rb[i].y), f2tf(rb[i].z), f2tf(rb[i].w));
            *(uint4*)&sA[bo + soff[i]] = va;
            *(uint4*)&sB[bo + soff[i]] = vb;
        }
        __syncthreads();
        if (kt + 1 < NKT) { loadA(kt + 1); loadB(kt + 1); }

        const unsigned boB = (unsigned)(bo * 4);
        #pragma unroll
        for (int ks = 0; ks < 4; ++ks) {
            unsigned afr[2][4];
            #pragma unroll
            for (int mt = 0; mt < 2; ++mt)
                ldsm_x4(afr[mt][0], afr[mt][1], afr[mt][2], afr[mt][3],
                        aAddr[mt] + boB + ks * 32u);
            unsigned bfr[8][2];
            #pragma unroll
            for (int p = 0; p < 4; ++p)
                ldsm_x4(bfr[2 * p][0], bfr[2 * p][1], bfr[2 * p + 1][0], bfr[2 * p + 1][1],
                        bAddr[p] + boB + ks * 32u);
            #pragma unroll
            for (int mt = 0; mt < 2; ++mt)
                #pragma unroll
                for (int nt = 0; nt < 8; ++nt)
                    mma_tf32(acc[mt][nt], afr[mt], bfr[nt]);
        }
        buf ^= 1;
    }

    // epilogue
    #pragma unroll
    for (int mt = 0; mt < 2; ++mt) {
        int r0 = bM * 128 + wm * 32 + mt * 16 + grp;
        #pragma unroll
        for (int nt = 0; nt < 8; ++nt) {
            int col  = bN * 128 + wn * 64 + nt * 8 + qid * 2;
            int colL = wn * 64 + nt * 8 + qid * 2;
            if (MODE == 0) {
                float b0 = sBias[colL];
                float b1 = sBias[colL + 1];
                float x0 = acc[mt][nt][0] + b0;
                float x1 = acc[mt][nt][1] + b1;
                float x2 = acc[mt][nt][2] + b0;
                float x3 = acc[mt][nt][3] + b1;
                if (grp == 0) {   // rows with r0 % 8 == 0 are t==0: relu (step 0 folded)
                    x0 = fmaxf(x0, 0.f); x1 = fmaxf(x1, 0.f);
                    x2 = fmaxf(x2, 0.f); x3 = fmaxf(x3, 0.f);
                }
                *(float2*)(C + (size_t)r0 * LDC + col)       = make_float2(x0, x1);
                *(float2*)(C + (size_t)(r0 + 8) * LDC + col) = make_float2(x2, x3);
            } else {
                float* p0 = C + (size_t)r0 * LDC + col;
                float* p1 = C + (size_t)(r0 + 8) * LDC + col;
                float2 g0 = *(float2*)p0;
                float2 g1 = *(float2*)p1;
                *(float2*)p0 = make_float2(fmaxf(acc[mt][nt][0] + g0.x, 0.f),
                                           fmaxf(acc[mt][nt][1] + g0.y, 0.f));
                *(float2*)p1 = make_float2(fmaxf(acc[mt][nt][2] + g1.x, 0.f),
                                           fmaxf(acc[mt][nt][3] + g1.y, 0.f));
            }
        }
    }
}

// need[h, b] = out[b, 7, h]   (out row stride 8192, t=7 offset 7168)
__global__ void transpose_k(const float* __restrict__ out, float* __restrict__ need)
{
    __shared__ float tile[32][33];
    int h0 = blockIdx.x * 32;
    int b0 = blockIdx.y * 32;
    int x = threadIdx.x;
    int y = threadIdx.y;
    #pragma unroll
    for (int j = 0; j < 32; j += 8)
        tile[y + j][x] = out[(size_t)(b0 + y + j) * 8192 + 7168 + h0 + x];
    __syncthreads();
    #pragma unroll
    for (int j = 0; j < 32; j += 8)
        need[(size_t)(h0 + y + j) * 8192 + b0 + x] = tile[x][y + j];
}

extern "C" void kernel_launch(void* const* d_in, const int* in_sizes, int n_in,
                              void* d_out, int out_size)
{
    const float* entity   = (const float*)d_in[0];  // [8192, 8, 512]
    const float* relation = (const float*)d_in[1];  // [8192, 8, 1024]
    const float* We       = (const float*)d_in[2];  // [1024, 512]
    const float* be       = (const float*)d_in[3];  // [1024]
    const float* Wr       = (const float*)d_in[4];  // [1024, 1024]
    const float* br       = (const float*)d_in[5];  // [1024]
    const float* Wh       = (const float*)d_in[6];  // [1024, 1024]
    const float* bh       = (const float*)d_in[7];  // [1024]

    float* out  = (float*)d_out;               // [8192, 8, 1024] = [65536, 1024]
    float* need = out + (size_t)65536 * 1024;  // [1024, 8192]

    const int smemBytes = (4 * BUFW + 128) * 4;  // 74240
    cudaFuncSetAttribute(gemm_k<0>, cudaFuncAttributeMaxDynamicSharedMemorySize, smemBytes);
    cudaFuncSetAttribute(gemm_k<1>, cudaFuncAttributeMaxDynamicSharedMemorySize, smemBytes);

    // Projection: g (all biases folded, relu applied for t==0 rows)
    gemm_k<0><<<dim3(8, 512), 256, smemBytes>>>(entity, relation, We, Wr, be, br, bh, out);

    // Recurrence: t = 1..7, in place over the g slices
    for (int t = 1; t < 8; ++t) {
        const float* Aprev = out + (size_t)(t - 1) * 1024;
        float*       Ct    = out + (size_t)t * 1024;
        gemm_k<1><<<dim3(8, 64), 256, smemBytes>>>(Aprev, nullptr, Wh, nullptr,
                                                   nullptr, nullptr, nullptr, Ct);
    }

    // need = h_7^T
    transpose_k<<<dim3(32, 256), dim3(32, 8)>>>(out, need);
}